// round 12
// baseline (speedup 1.0000x reference)
#include <cuda_runtime.h>

// Problem constants (fixed by the reference: B=32, H=W=1024)
#define BB 32
#define HH 1024
#define WW 1024
#define RPB 8           // rows per block
#define NTHREADS 256    // 256 threads * 4 px = 1024 = one full row width

__device__ double g_sum;

__global__ void zero_kernel() { g_sum = 0.0; }

__global__ __launch_bounds__(NTHREADS)
void bbce_kernel(const float* __restrict__ pred, const float* __restrict__ tgt) {
    const int tilesPerImg = HH / RPB;
    const int tile = blockIdx.x;
    const int b  = tile / tilesPerImg;
    const int y0 = (tile - b * tilesPerImg) * RPB;

    const size_t base = (size_t)b * HH * WW;
    const float* tb = tgt  + base;
    const float* pb = pred + base;

    const int x0 = threadIdx.x * 4;
    const bool hasL = (x0 > 0);
    const bool hasR = (x0 + 4 < WW);

    float acc = 0.f;

    #pragma unroll 2
    for (int r = 0; r < RPB; ++r) {
        const int y = y0 + r;
        const bool hasT = (y > 0);
        const bool hasB = (y < HH - 1);

        const float* rowM = tb + (size_t)y * WW + x0;

        // Vertical max/min over the (present) 3 rows, for columns x0-1 .. x0+4.
        // Pad identities for binary data: 0 for max, 1 for min.
        float vmx[6], vmn[6];

        float4 tm = *(const float4*)rowM;
        vmx[1] = tm.x; vmx[2] = tm.y; vmx[3] = tm.z; vmx[4] = tm.w;
        vmn[1] = tm.x; vmn[2] = tm.y; vmn[3] = tm.z; vmn[4] = tm.w;

        if (hasL) { float v = rowM[-1]; vmx[0] = v;  vmn[0] = v;  }
        else      {                    vmx[0] = 0.f; vmn[0] = 1.f; }
        if (hasR) { float v = rowM[4];  vmx[5] = v;  vmn[5] = v;  }
        else      {                    vmx[5] = 0.f; vmn[5] = 1.f; }

        if (hasT) {
            const float* rowT = rowM - WW;
            float4 t = *(const float4*)rowT;
            vmx[1] = fmaxf(vmx[1], t.x); vmn[1] = fminf(vmn[1], t.x);
            vmx[2] = fmaxf(vmx[2], t.y); vmn[2] = fminf(vmn[2], t.y);
            vmx[3] = fmaxf(vmx[3], t.z); vmn[3] = fminf(vmn[3], t.z);
            vmx[4] = fmaxf(vmx[4], t.w); vmn[4] = fminf(vmn[4], t.w);
            if (hasL) { float v = rowT[-1]; vmx[0] = fmaxf(vmx[0], v); vmn[0] = fminf(vmn[0], v); }
            if (hasR) { float v = rowT[4];  vmx[5] = fmaxf(vmx[5], v); vmn[5] = fminf(vmn[5], v); }
        }
        if (hasB) {
            const float* rowB = rowM + WW;
            float4 t = *(const float4*)rowB;
            vmx[1] = fmaxf(vmx[1], t.x); vmn[1] = fminf(vmn[1], t.x);
            vmx[2] = fmaxf(vmx[2], t.y); vmn[2] = fminf(vmn[2], t.y);
            vmx[3] = fmaxf(vmx[3], t.z); vmn[3] = fminf(vmn[3], t.z);
            vmx[4] = fmaxf(vmx[4], t.w); vmn[4] = fminf(vmn[4], t.w);
            if (hasL) { float v = rowB[-1]; vmx[0] = fmaxf(vmx[0], v); vmn[0] = fminf(vmn[0], v); }
            if (hasR) { float v = rowB[4];  vmx[5] = fmaxf(vmx[5], v); vmn[5] = fminf(vmn[5], v); }
        }

        // Horizontal 3-wide combine -> full 3x3 window max/min
        float4 p = *(const float4*)(pb + (size_t)y * WW + x0);

        float tarr[4] = { tm.x, tm.y, tm.z, tm.w };
        float parr[4] = { p.x,  p.y,  p.z,  p.w  };

        #pragma unroll
        for (int i = 0; i < 4; ++i) {
            float hmx = fmaxf(fmaxf(vmx[i], vmx[i + 1]), vmx[i + 2]);
            float hmn = fminf(fminf(vmn[i], vmn[i + 1]), vmn[i + 2]);
            float w = (hmx - hmn > 0.f) ? 3.0f : 1.0f;
            float t = tarr[i];
            // q = t ? p : (1-p), branch-free and exact for t in {0,1}
            float q = fmaf(2.0f * t, parr[i], (1.0f - t) - parr[i]);
            // bce = -log(q); acc += w * bce
            acc = fmaf(-w, __logf(q), acc);
        }
    }

    // Block reduction: warp shuffle then smem across warps, then one
    // double atomicAdd per block.
    #pragma unroll
    for (int o = 16; o > 0; o >>= 1)
        acc += __shfl_xor_sync(0xFFFFFFFFu, acc, o);

    __shared__ float wsum[NTHREADS / 32];
    const int lane = threadIdx.x & 31;
    const int wid  = threadIdx.x >> 5;
    if (lane == 0) wsum[wid] = acc;
    __syncthreads();
    if (threadIdx.x == 0) {
        float s = 0.f;
        #pragma unroll
        for (int i = 0; i < NTHREADS / 32; ++i) s += wsum[i];
        atomicAdd(&g_sum, (double)s);
    }
}

__global__ void finalize_kernel(float* __restrict__ out) {
    const double n = (double)((size_t)BB * HH * WW);
    out[0] = (float)(g_sum / n);
}

extern "C" void kernel_launch(void* const* d_in, const int* in_sizes, int n_in,
                              void* d_out, int out_size) {
    const float* pred = (const float*)d_in[0];
    const float* tgt  = (const float*)d_in[1];
    float* out = (float*)d_out;

    zero_kernel<<<1, 1>>>();
    bbce_kernel<<<BB * (HH / RPB), NTHREADS>>>(pred, tgt);
    finalize_kernel<<<1, 1>>>(out);
}

// round 15
// speedup vs baseline: 1.0568x; 1.0568x over previous
#include <cuda_runtime.h>

// Problem constants (fixed by the reference: B=32, H=W=1024)
#define BB 32
#define HH 1024
#define WW 1024
#define RPB 16          // rows per block tile
#define NTHREADS 256    // 256 threads * 4 px = 1024 = one full row width
#define NBLOCKS (BB * (HH / RPB))   // 2048

// Per-block partial sums (every block writes its slot -> no zeroing needed)
__device__ float g_part[NBLOCKS];

__global__ __launch_bounds__(NTHREADS)
void bbce_kernel(const float* __restrict__ pred, const float* __restrict__ tgt) {
    const int tile = blockIdx.x;
    const int b  = tile >> 6;            // / (HH/RPB) = /64
    const int y0 = (tile & 63) * RPB;

    const size_t base = (size_t)b * HH * WW;
    const float* tb = tgt  + base;
    const float* pb = pred + base;

    const int x0   = threadIdx.x * 4;
    const int lane = threadIdx.x & 31;
    const bool isL  = (lane == 0);
    const bool isR  = (lane == 31);
    const bool hasL = (x0 > 0);
    const bool hasR = (x0 + 4 < WW);

    // Per-pixel valid-column count (2 at the image's left/right edge, else 3)
    float cv[4];
    #pragma unroll
    for (int i = 0; i < 4; ++i) {
        const int x = x0 + i;
        cv[i] = (x == 0 || x == WW - 1) ? 2.f : 3.f;
    }

    // Rolling target rows (0-padded outside the image: identity for sum)
    float4 tP, tC, tN;
    float lP = 0.f, lC = 0.f, lN = 0.f;   // left halo scalar (lane 0 only)
    float rP = 0.f, rC = 0.f, rN = 0.f;   // right halo scalar (lane 31 only)

    // Prologue: rows y0-1 and y0
    if (y0 > 0) {
        tP = *(const float4*)(tb + (size_t)(y0 - 1) * WW + x0);
        lP = (isL && hasL) ? tb[(size_t)(y0 - 1) * WW + x0 - 1] : 0.f;
        rP = (isR && hasR) ? tb[(size_t)(y0 - 1) * WW + x0 + 4] : 0.f;
    } else {
        tP = make_float4(0.f, 0.f, 0.f, 0.f);
    }
    tC = *(const float4*)(tb + (size_t)y0 * WW + x0);
    lC = (isL && hasL) ? tb[(size_t)y0 * WW + x0 - 1] : 0.f;
    rC = (isR && hasR) ? tb[(size_t)y0 * WW + x0 + 4] : 0.f;

    float acc = 0.f;

    #pragma unroll 4
    for (int r = 0; r < RPB; ++r) {
        const int y  = y0 + r;
        const int y1 = y + 1;

        if (y1 < HH) {
            tN = *(const float4*)(tb + (size_t)y1 * WW + x0);
            lN = (isL && hasL) ? tb[(size_t)y1 * WW + x0 - 1] : 0.f;
            rN = (isR && hasR) ? tb[(size_t)y1 * WW + x0 + 4] : 0.f;
        } else {
            tN = make_float4(0.f, 0.f, 0.f, 0.f);
            lN = 0.f; rN = 0.f;
        }

        // Vertical window sums (exact small integers in f32)
        float4 vs;
        vs.x = tP.x + tC.x + tN.x;
        vs.y = tP.y + tC.y + tN.y;
        vs.z = tP.z + tC.z + tN.z;
        vs.w = tP.w + tC.w + tN.w;
        const float lsum = lP + lC + lN;
        const float rsum = rP + rC + rN;

        // Neighbor columns via shuffle; warp-edge lanes use their own rolling halo
        float lh = __shfl_up_sync(0xFFFFFFFFu, vs.w, 1);
        float rh = __shfl_down_sync(0xFFFFFFFFu, vs.x, 1);
        if (isL) lh = lsum;   // 0 when !hasL -> matches cv=2 accounting
        if (isR) rh = rsum;

        // Valid-row count for this window (2 at top/bottom image edge)
        float rv = 3.f;
        if (y == 0 || y == HH - 1) rv = 2.f;

        const float4 p = *(const float4*)(pb + (size_t)y * WW + x0);

        const float h[6]    = { lh, vs.x, vs.y, vs.z, vs.w, rh };
        const float tarr[4] = { tC.x, tC.y, tC.z, tC.w };
        const float parr[4] = { p.x, p.y, p.z, p.w };

        #pragma unroll
        for (int i = 0; i < 4; ++i) {
            const float s   = h[i] + h[i + 1] + h[i + 2];
            const float cnt = rv * cv[i];
            // boundary <=> window has both 0s and 1s <=> 0 < sum < validCount
            const float w = (s > 0.f && s < cnt) ? 3.0f : 1.0f;
            const float t = tarr[i];
            // q = t ? p : (1-p), branch-free and exact for t in {0,1}
            const float q = fmaf(2.0f * t, parr[i], (1.0f - t) - parr[i]);
            acc = fmaf(-w, __logf(q), acc);
        }

        // rotate rolling state
        tP = tC; tC = tN;
        lP = lC; lC = lN;
        rP = rC; rC = rN;
    }

    // Block reduction: warp shuffle then smem across warps
    #pragma unroll
    for (int o = 16; o > 0; o >>= 1)
        acc += __shfl_xor_sync(0xFFFFFFFFu, acc, o);

    __shared__ float wsum[NTHREADS / 32];
    const int wid = threadIdx.x >> 5;
    if (lane == 0) wsum[wid] = acc;
    __syncthreads();
    if (threadIdx.x == 0) {
        float s = 0.f;
        #pragma unroll
        for (int i = 0; i < NTHREADS / 32; ++i) s += wsum[i];
        g_part[blockIdx.x] = s;
    }
}

__global__ __launch_bounds__(256)
void finalize_kernel(float* __restrict__ out) {
    // 2048 partials, 256 threads: 8 each, accumulate in double
    double d = 0.0;
    #pragma unroll
    for (int i = 0; i < NBLOCKS / 256; ++i)
        d += (double)g_part[threadIdx.x + i * 256];

    #pragma unroll
    for (int o = 16; o > 0; o >>= 1)
        d += __shfl_xor_sync(0xFFFFFFFFu, d, o);

    __shared__ double wsum[8];
    const int lane = threadIdx.x & 31;
    const int wid  = threadIdx.x >> 5;
    if (lane == 0) wsum[wid] = d;
    __syncthreads();
    if (threadIdx.x == 0) {
        double s = 0.0;
        #pragma unroll
        for (int i = 0; i < 8; ++i) s += wsum[i];
        const double n = (double)((size_t)BB * HH * WW);
        out[0] = (float)(s / n);
    }
}

extern "C" void kernel_launch(void* const* d_in, const int* in_sizes, int n_in,
                              void* d_out, int out_size) {
    const float* pred = (const float*)d_in[0];
    const float* tgt  = (const float*)d_in[1];
    float* out = (float*)d_out;

    bbce_kernel<<<NBLOCKS, NTHREADS>>>(pred, tgt);
    finalize_kernel<<<1, 256>>>(out);
}